// round 17
// baseline (speedup 1.0000x reference)
#include <cuda_runtime.h>
#include <cstdint>

#define NEGV (-1e30f)
#define LOG2E 1.4426950408889634f
#define LN2   0.6931471805599453f
#define CHUNK 8
#define TT    64            // t-tile per gather block

// Static device scratch (allocation APIs are forbidden).
__device__ float    g_emit[12u * 1024u * 1024u];  // e[t][n][256], slot = state
__device__ float    g_alpha[1024 * 256];
__device__ float    g_gamma[1024 * 256];
__device__ unsigned g_fb_ctr;                      // zero-init; reset each call

__device__ __forceinline__ float ex2f(float x) {
    float y; asm("ex2.approx.ftz.f32 %0, %1;" : "=f"(y) : "f"(x)); return y;
}
__device__ __forceinline__ float lg2f(float x) {
    float y; asm("lg2.approx.ftz.f32 %0, %1;" : "=f"(y) : "f"(x)); return y;
}
__device__ __forceinline__ float lae3(float x0, float x1, float x2) {
    float m01 = fmaxf(x0, x1), n01 = fminf(x0, x1);
    float hi  = fmaxf(m01, x2);
    float lo  = fminf(n01, x2);
    float md  = fmaxf(n01, fminf(m01, x2));
    return hi + lg2f(1.0f + ex2f(md - hi) + ex2f(lo - hi));
}
__device__ __forceinline__ float lae2(float x0, float x1) {
    float hi = fmaxf(x0, x1);
    float lo = fminf(x0, x1);
    return hi + lg2f(1.0f + ex2f(lo - hi));
}

// ---------------------------------------------------------------------------
// Phase 1: emission gather (unchanged from R16).
// ---------------------------------------------------------------------------
__global__ void gather_kernel(const float* __restrict__ lp,
                              const int*   __restrict__ targets,
                              int N, int C, int L, int S, int T) {
    const int n  = blockIdx.y;
    const int t0 = blockIdx.x * TT;
    const int s  = threadIdx.x;

    const bool valid = (s < S);
    int lab = 0;
    if (valid && (s & 1)) lab = __ldg(&targets[n * L + (s >> 1)]);
    const float* src = lp + (size_t)n * C + lab;
    const size_t lstride = (size_t)N * C;

    for (int u = 0; u < TT; u += 8) {
        float v[8];
#pragma unroll
        for (int j = 0; j < 8; ++j) {
            int tt = t0 + u + j;
            v[j] = (valid && tt < T) ? __ldg(src + (size_t)tt * lstride) * LOG2E
                                     : NEGV;
        }
#pragma unroll
        for (int j = 0; j < 8; ++j) {
            int tt = t0 + u + j;
            if (tt < T) g_emit[((size_t)tt * N + n) * 256 + s] = v[j];
        }
    }
}

// ---------------------------------------------------------------------------
// Phase 2: fused fwd+bwd — ONE CTA per utterance, 4 warps, 2 states/lane,
// halo-recompute zones. Each step advances BOTH chains (fills latency
// bubbles of one chain with the other's instructions).
// ---------------------------------------------------------------------------
__device__ __forceinline__ void issue_dir(const float* ecov, size_t tstride,
                                          float (*buf)[CHUNK][64], int lane,
                                          int b, int i0, int imax,
                                          bool desc, int tbase) {
    if (lane < 16) {
#pragma unroll
        for (int j = 0; j < CHUNK; ++j) {
            int ii = i0 + j;
            if (ii > imax) ii = imax;
            if (ii < 0)    ii = 0;
            int tt = desc ? (tbase - ii) : ii;
            const float* src = ecov + (size_t)tt * tstride + lane * 4;
            uint32_t dst = (uint32_t)__cvta_generic_to_shared(&buf[b][j][lane * 4]);
            asm volatile("cp.async.cg.shared.global [%0], [%1], 16;"
                         :: "r"(dst), "l"(src));
        }
    }
}
__device__ __forceinline__ void commit_g() {
    asm volatile("cp.async.commit_group;" ::: "memory");
}

__global__ void __launch_bounds__(128, 1)
fb_kernel(const int* __restrict__ targets,
          const int* __restrict__ il,
          const int* __restrict__ tl,
          float*     __restrict__ out,
          int N, int L) {
    __shared__ float smf[4][2][CHUNK][64];    // fwd FIFO per warp
    __shared__ float smb[4][2][CHUNK][64];    // bwd FIFO per warp
    __shared__ float xf[2][3][16];            // fwd zone exchange
    __shared__ float xbf[2][3][16];           // bwd zone exchange

    const int  n    = blockIdx.x;
    const int  w    = threadIdx.x >> 5;
    const int  lane = threadIdx.x & 31;
    const int  S    = 2 * L + 1;

    const int ilen  = il[n];
    const int s_end = 2 * tl[n];
    const int m     = (ilen - 1) >> 1;        // fwd covers t = 0..m
    const int K     = ilen - 2 - m;           // bwd steps (K = m or m-1)

    const int covw = 48 * w;
    const int base = covw + lane * 2;         // even -> a[0] is blank

    const float* ecov    = g_emit + (size_t)n * 256 + covw;
    const float* ebase   = g_emit + (size_t)n * 256 + base;
    const size_t tstride = (size_t)N * 256;
    float (*buf_f)[CHUNK][64] = smf[w];
    float (*buf_b)[CHUNK][64] = smb[w];

    // skip edges for the odd state base+1
    bool skip1 = false, bskip1 = false;
    {
        int s = base + 1;
        if (s < S && s >= 3)
            skip1 = (__ldg(&targets[n * L + (s >> 1)]) !=
                     __ldg(&targets[n * L + (s >> 1) - 1]));
        if (s < S && (s >> 1) + 1 <= L - 1)
            bskip1 = (__ldg(&targets[n * L + (s >> 1)]) !=
                      __ldg(&targets[n * L + (s >> 1) + 1]));
    }

    // ---- inits ----
    float a_f[2], a_b[2];
    {   // fwd t = 0
        float2 E = __ldg((const float2*)ebase);
        a_f[0] = (base     <= 1) ? E.x : NEGV;
        a_f[1] = (base + 1 <= 1) ? E.y : NEGV;
    }
    if (ilen == 1) {          // bwd empty: gamma = 0 on accepting states
        a_b[0] = (base     == s_end || (s_end >= 1 && base     == s_end - 1)) ? 0.0f : NEGV;
        a_b[1] = (base + 1 == s_end || (s_end >= 1 && base + 1 == s_end - 1)) ? 0.0f : NEGV;
    } else {                  // beta init at t = ilen-1
        float2 E = __ldg((const float2*)(ebase + (size_t)(ilen - 1) * tstride));
        a_b[0] = (base     == s_end || (s_end >= 1 && base     == s_end - 1)) ? E.x : NEGV;
        a_b[1] = (base + 1 == s_end || (s_end >= 1 && base + 1 == s_end - 1)) ? E.y : NEGV;
    }

    // ---- main fused recursion ----
    if (m >= 1 || K >= 1) {
        issue_dir(ecov, tstride, buf_f, lane, 0, 1, m, false, 0);
        issue_dir(ecov, tstride, buf_b, lane, 0, 1, K, true, ilen - 1);
        commit_g();
        issue_dir(ecov, tstride, buf_f, lane, 1, 1 + CHUNK, m, false, 0);
        issue_dir(ecov, tstride, buf_b, lane, 1, 1 + CHUNK, K, true, ilen - 1);
        commit_g();

        int t = 1, k = 1, b = 0, xb = 0;
        const int nc    = (K < m) ? (K < 0 ? 0 : K) : m;   // min(m, max(K,0))
        const int nfull = nc / CHUNK;

        for (int c = 0; c < nfull; ++c) {
            // zone exchanges, one barrier for both directions
            xb ^= 1;
            if (w < 3 && lane >= 24) {               // fwd: w -> w+1
                xf[xb][w][(lane - 24) * 2]     = a_f[0];
                xf[xb][w][(lane - 24) * 2 + 1] = a_f[1];
            }
            if (w >= 1 && lane < 8) {                // bwd: w -> w-1
                xbf[xb][w - 1][lane * 2]     = a_b[0];
                xbf[xb][w - 1][lane * 2 + 1] = a_b[1];
            }
            __syncthreads();
            if (w > 0 && lane < 8) {
                a_f[0] = xf[xb][w - 1][lane * 2];
                a_f[1] = xf[xb][w - 1][lane * 2 + 1];
            }
            if (w < 3 && lane >= 24) {
                a_b[0] = xbf[xb][w][(lane - 24) * 2];
                a_b[1] = xbf[xb][w][(lane - 24) * 2 + 1];
            }

            asm volatile("cp.async.wait_group 1;" ::: "memory");
            __syncwarp();
            float2 Ef[CHUNK], Eb[CHUNK];
#pragma unroll
            for (int j = 0; j < CHUNK; ++j) {
                Ef[j] = *(const float2*)&buf_f[b][j][lane * 2];
                Eb[j] = *(const float2*)&buf_b[b][j][lane * 2];
            }
            __syncwarp();
            issue_dir(ecov, tstride, buf_f, lane, b, t + 2 * CHUNK, m, false, 0);
            issue_dir(ecov, tstride, buf_b, lane, b, k + 2 * CHUNK, K, true, ilen - 1);
            commit_g();
            b ^= 1;
#pragma unroll
            for (int j = 0; j < CHUNK; ++j) {        // branchless, both chains
                // fwd step
                float s1 = __shfl_up_sync(0xffffffffu, a_f[1], 1);
                if (lane == 0) s1 = NEGV;
                float f1n = lae3(a_f[1], a_f[0], skip1 ? s1 : NEGV) + Ef[j].y;
                a_f[0] = lae2(a_f[0], s1) + Ef[j].x;
                a_f[1] = f1n;
                // bwd step
                float d0 = __shfl_down_sync(0xffffffffu, a_b[0], 1);
                float d1 = __shfl_down_sync(0xffffffffu, a_b[1], 1);
                if (lane == 31) { d0 = NEGV; d1 = NEGV; }
                float b0n = lae2(a_b[0], a_b[1]) + Eb[j].x;
                a_b[1] = lae3(a_b[1], d0, bskip1 ? d1 : NEGV) + Eb[j].y;
                a_b[0] = b0n;
            }
            t += CHUNK; k += CHUNK;
        }

        if (t <= m || k <= K) {    // unified guarded tail (<= CHUNK steps each)
            xb ^= 1;
            if (w < 3 && lane >= 24) {
                xf[xb][w][(lane - 24) * 2]     = a_f[0];
                xf[xb][w][(lane - 24) * 2 + 1] = a_f[1];
            }
            if (w >= 1 && lane < 8) {
                xbf[xb][w - 1][lane * 2]     = a_b[0];
                xbf[xb][w - 1][lane * 2 + 1] = a_b[1];
            }
            __syncthreads();
            if (w > 0 && lane < 8) {
                a_f[0] = xf[xb][w - 1][lane * 2];
                a_f[1] = xf[xb][w - 1][lane * 2 + 1];
            }
            if (w < 3 && lane >= 24) {
                a_b[0] = xbf[xb][w][(lane - 24) * 2];
                a_b[1] = xbf[xb][w][(lane - 24) * 2 + 1];
            }
            asm volatile("cp.async.wait_group 1;" ::: "memory");
            __syncwarp();
            float2 Ef[CHUNK], Eb[CHUNK];
#pragma unroll
            for (int j = 0; j < CHUNK; ++j) {
                Ef[j] = *(const float2*)&buf_f[b][j][lane * 2];
                Eb[j] = *(const float2*)&buf_b[b][j][lane * 2];
            }
#pragma unroll
            for (int j = 0; j < CHUNK; ++j) {
                if (t <= m) {
                    float s1 = __shfl_up_sync(0xffffffffu, a_f[1], 1);
                    if (lane == 0) s1 = NEGV;
                    float f1n = lae3(a_f[1], a_f[0], skip1 ? s1 : NEGV) + Ef[j].y;
                    a_f[0] = lae2(a_f[0], s1) + Ef[j].x;
                    a_f[1] = f1n;
                    ++t;
                }
                if (k <= K) {
                    float d0 = __shfl_down_sync(0xffffffffu, a_b[0], 1);
                    float d1 = __shfl_down_sync(0xffffffffu, a_b[1], 1);
                    if (lane == 31) { d0 = NEGV; d1 = NEGV; }
                    float b0n = lae2(a_b[0], a_b[1]) + Eb[j].x;
                    a_b[1] = lae3(a_b[1], d0, bskip1 ? d1 : NEGV) + Eb[j].y;
                    a_b[0] = b0n;
                    ++k;
                }
            }
        }
    }

    // ---- fwd: store alpha (ownership + padding as R16) ----
    if (w == 0 || lane >= 8) {
        g_alpha[n * 256 + base]     = a_f[0];
        g_alpha[n * 256 + base + 1] = a_f[1];
    }
    if (w >= 1 && lane < 8) {
        int p = 208 + (w - 1) * 16 + lane * 2;
        g_alpha[n * 256 + p]     = NEGV;
        g_alpha[n * 256 + p + 1] = NEGV;
    }

    // ---- bwd: final zone exchange + gamma (transition-only), then store ----
    if (ilen > 1) {
        if (w >= 1 && lane < 8) {
            xbf[0][w - 1][lane * 2]     = a_b[0];
            xbf[0][w - 1][lane * 2 + 1] = a_b[1];
        }
        __syncthreads();
        if (w < 3 && lane >= 24) {
            a_b[0] = xbf[0][w][(lane - 24) * 2];
            a_b[1] = xbf[0][w][(lane - 24) * 2 + 1];
        }
        float d0 = __shfl_down_sync(0xffffffffu, a_b[0], 1);
        float d1 = __shfl_down_sync(0xffffffffu, a_b[1], 1);
        if (lane == 31) { d0 = NEGV; d1 = NEGV; }
        float b0n = lae2(a_b[0], a_b[1]);
        a_b[1] = lae3(a_b[1], d0, bskip1 ? d1 : NEGV);
        a_b[0] = b0n;
    }
    if (w == 3 || lane < 24) {
        g_gamma[n * 256 + base]     = a_b[0];
        g_gamma[n * 256 + base + 1] = a_b[1];
    }
    if (w < 3 && lane >= 24) {
        int p = 208 + w * 16 + (lane - 24) * 2;
        g_gamma[n * 256 + p]     = NEGV;
        g_gamma[n * 256 + p + 1] = NEGV;
    }

    // ---- finisher: last block combines (per-n logsumexp) + fixed-order sum ----
    __threadfence();
    unsigned done = 0;
    if (threadIdx.x == 0)
        done = (atomicAdd(&g_fb_ctr, 1u) == (unsigned)N - 1u);
    done = __shfl_sync(0xffffffffu, done, 0);
    if (w == 0 && done) {
        __threadfence();
        float acc = 0.0f;
        for (int nn = 0; nn < N; ++nn) {
            float v[8];
            float mx = -3.4e38f;
#pragma unroll
            for (int kk = 0; kk < 8; ++kk) {
                v[kk] = g_alpha[nn * 256 + lane + 32 * kk]
                      + g_gamma[nn * 256 + lane + 32 * kk];
                mx = fmaxf(mx, v[kk]);
            }
#pragma unroll
            for (int o = 16; o > 0; o >>= 1)
                mx = fmaxf(mx, __shfl_xor_sync(0xffffffffu, mx, o));
            float sum = 0.0f;
#pragma unroll
            for (int kk = 0; kk < 8; ++kk)
                sum += (v[kk] - mx > -120.0f) ? ex2f(v[kk] - mx) : 0.0f;
#pragma unroll
            for (int o = 16; o > 0; o >>= 1)
                sum += __shfl_xor_sync(0xffffffffu, sum, o);
            float tot = (mx + lg2f(sum)) * LN2;
            if (lane == 0 && tot > -1e29f) acc += tot;
        }
        if (lane == 0) {
            out[0] = -acc;
            g_fb_ctr = 0u;
            __threadfence();
        }
    }
}

extern "C" void kernel_launch(void* const* d_in, const int* in_sizes, int n_in,
                              void* d_out, int out_size) {
    const float* lp      = (const float*)d_in[0];
    const int*   targets = (const int*)d_in[1];
    const int*   il      = (const int*)d_in[2];
    const int*   tl      = (const int*)d_in[3];

    const int N = in_sizes[2];
    const int L = in_sizes[1] / N;        // 100
    const int C = 1024;                   // fixed for this problem id
    const int T = in_sizes[0] / (N * C);  // 1500
    const int S = 2 * L + 1;              // 201 (needs S <= 208)

    dim3 ggrid((T + TT - 1) / TT, N);
    gather_kernel<<<ggrid, 256>>>(lp, targets, N, C, L, S, T);
    fb_kernel<<<N, 128>>>(targets, il, tl, (float*)d_out, N, L);
}